// round 14
// baseline (speedup 1.0000x reference)
#include <cuda_runtime.h>
#include <cuda_bf16.h>
#include <math.h>
#include <stdint.h>

constexpr int T  = 2048;
constexpr int B  = 4;
constexpr int E  = 1024;
constexpr int H  = 16;
constexpr int D  = 64;
constexpr int BH = B * H;

constexpr size_t QKV_ELEMS  = (size_t)T * B * 3 * E;
constexpr size_t HEAD_ELEMS = (size_t)BH * T * D;
constexpr size_t OUT_ELEMS  = (size_t)T * B * E;
constexpr size_t ATTN_ELEMS = (size_t)BH * T * T;

__device__ float g_qkv [QKV_ELEMS];
__device__ float g_attn[ATTN_ELEMS];
__device__ __nv_bfloat16 g_inh[OUT_ELEMS],  g_inl[OUT_ELEMS];
__device__ __nv_bfloat16 g_wih[3*E*E],      g_wil[3*E*E];
__device__ __nv_bfloat16 g_woh[E*E],        g_wol[E*E];
__device__ __nv_bfloat16 g_qh [HEAD_ELEMS], g_ql [HEAD_ELEMS];
__device__ __nv_bfloat16 g_kh [HEAD_ELEMS], g_kl [HEAD_ELEMS];
__device__ __nv_bfloat16 g_vTh[HEAD_ELEMS], g_vTl[HEAD_ELEMS];
__device__ __nv_bfloat16 g_cxh[OUT_ELEMS],  g_cxl[OUT_ELEMS];

// ---------------------------------------------------------------------------
__device__ __forceinline__ uint32_t smem_u32(const void* p) {
    uint32_t a;
    asm("{ .reg .u64 t; cvta.to.shared.u64 t, %1; cvt.u32.u64 %0, t; }"
        : "=r"(a) : "l"(p));
    return a;
}
__device__ __forceinline__ void ldm_x4(uint32_t& r0, uint32_t& r1,
                                       uint32_t& r2, uint32_t& r3, uint32_t addr) {
    asm volatile("ldmatrix.sync.aligned.m8n8.x4.shared.b16 {%0,%1,%2,%3}, [%4];"
                 : "=r"(r0), "=r"(r1), "=r"(r2), "=r"(r3) : "r"(addr));
}
__device__ __forceinline__ void mma16816(float* c, const uint32_t* a,
                                         const uint32_t* b) {
    asm volatile(
        "mma.sync.aligned.m16n8k16.row.col.f32.bf16.bf16.f32 "
        "{%0,%1,%2,%3}, {%4,%5,%6,%7}, {%8,%9}, {%0,%1,%2,%3};"
        : "+f"(c[0]), "+f"(c[1]), "+f"(c[2]), "+f"(c[3])
        : "r"(a[0]), "r"(a[1]), "r"(a[2]), "r"(a[3]), "r"(b[0]), "r"(b[1]));
}
__device__ __forceinline__ void cp16(uint32_t dst, const void* src) {
    asm volatile("cp.async.cg.shared.global [%0], [%1], 16;" :: "r"(dst), "l"(src));
}
__device__ __forceinline__ void cp_commit() { asm volatile("cp.async.commit_group;"); }
template<int N> __device__ __forceinline__ void cp_wait() {
    asm volatile("cp.async.wait_group %0;" :: "n"(N));
}
__device__ __forceinline__ uint32_t packbf2(__nv_bfloat16 a, __nv_bfloat16 b) {
    __nv_bfloat162 t(a, b);
    return *reinterpret_cast<uint32_t*>(&t);
}
__device__ __forceinline__ void split_bf(float x, __nv_bfloat16& h, __nv_bfloat16& l) {
    h = __float2bfloat16(x);
    l = __float2bfloat16(x - __bfloat162float(h));
}
// exp via FMA/ALU pipes (offload from MUFU). Valid |s| <~ 80; rel err ~3e-6.
__device__ __forceinline__ float exp_poly(float s) {
    const float y = s * 1.4426950408889634f;   // log2(e)
    const float r = rintf(y);
    const float f = y - r;
    const int   i = (int)r;
    float p = 0.00133335581f;
    p = fmaf(p, f, 0.00961812911f);
    p = fmaf(p, f, 0.0555041087f);
    p = fmaf(p, f, 0.240226507f);
    p = fmaf(p, f, 0.693147180f);
    p = fmaf(p, f, 1.0f);
    return p * __int_as_float((i + 127) << 23);
}

// ---------------------------------------------------------------------------
// Split fp32 -> bf16 hi/lo
// ---------------------------------------------------------------------------
__global__ __launch_bounds__(256) void split_kernel(
    const float* __restrict__ src, __nv_bfloat16* __restrict__ dh,
    __nv_bfloat16* __restrict__ dl, int n)
{
    int i = blockIdx.x * 2048 + threadIdx.x;
#pragma unroll
    for (int k = 0; k < 8; k++, i += 256) {
        if (i < n) {
            __nv_bfloat16 h, l;
            split_bf(src[i], h, l);
            dh[i] = h; dl[i] = l;
        }
    }
}

// ---------------------------------------------------------------------------
// GEMM (TN) on pre-split bf16:  C = A @ B^T (+bias).
// 128x128 tile, 256 threads (8 warps 2m x 4n), K-chunk 32, 2-stage cp.async.
// ---------------------------------------------------------------------------
constexpr int GST = 40;
constexpr int GBUF = 128 * GST * 2;          // 10240 B
constexpr int GSTAGE = 4 * GBUF;             // 40960 B
constexpr int GEMM_SMEM = 2 * GSTAGE;        // 81920 B

__global__ __launch_bounds__(256) void gemm_bf(
    const __nv_bfloat16* __restrict__ Ah, const __nv_bfloat16* __restrict__ Al,
    const __nv_bfloat16* __restrict__ Bh, const __nv_bfloat16* __restrict__ Bl,
    const float* __restrict__ bias, float* __restrict__ C, int K, int ldc)
{
    const int bx = blockIdx.x, by = blockIdx.y;
    extern __shared__ char sm[];
    const uint32_t su = smem_u32(sm);

    const int tid = threadIdx.x, lane = tid & 31, wid = tid >> 5;
    const int wm = wid & 1, wn = wid >> 1;
    const int lr16 = lane & 15, kc8 = (lane >> 4) << 3;
    const int g = lane >> 2, t4 = lane & 3;

    const __nv_bfloat16* gAh = Ah + (size_t)(by * 128) * K;
    const __nv_bfloat16* gAl = Al + (size_t)(by * 128) * K;
    const __nv_bfloat16* gBh = Bh + (size_t)(bx * 128) * K;
    const __nv_bfloat16* gBl = Bl + (size_t)(bx * 128) * K;

    auto issue = [&](int ch, int s) {
        const uint32_t sb = su + (uint32_t)s * GSTAGE;
        const int k0 = ch * 32;
#pragma unroll
        for (int i = 0; i < 2; i++) {
            const int seg = tid + i * 256;
            const int r = seg >> 2, c = seg & 3;
            const uint32_t so = (uint32_t)(r * GST + c * 8) * 2u;
            const size_t go = (size_t)r * K + k0 + c * 8;
            cp16(sb + so,            gAh + go);
            cp16(sb + GBUF + so,     gAl + go);
            cp16(sb + 2*GBUF + so,   gBh + go);
            cp16(sb + 3*GBUF + so,   gBl + go);
        }
        cp_commit();
    };

    float acc[4][4][4] = {};
    const int nch = K >> 5;
    issue(0, 0);

    for (int ch = 0; ch < nch; ch++) {
        cp_wait<0>();
        __syncthreads();
        if (ch + 1 < nch) issue(ch + 1, (ch + 1) & 1);

        const uint32_t sb = su + (uint32_t)(ch & 1) * GSTAGE;
#pragma unroll
        for (int ks = 0; ks < 2; ks++) {
            const int fk = ks * 16 + kc8;
            uint32_t bh[4][2], bl[4][2];
#pragma unroll
            for (int jj = 0; jj < 2; jj++) {
                const uint32_t off = (uint32_t)((wn*32 + jj*16 + lr16) * GST + fk) * 2u;
                ldm_x4(bh[2*jj][0], bh[2*jj+1][0], bh[2*jj][1], bh[2*jj+1][1],
                       sb + 2*GBUF + off);
                ldm_x4(bl[2*jj][0], bl[2*jj+1][0], bl[2*jj][1], bl[2*jj+1][1],
                       sb + 3*GBUF + off);
            }
#pragma unroll
            for (int i = 0; i < 4; i++) {
                const uint32_t off = (uint32_t)((wm*64 + i*16 + lr16) * GST + fk) * 2u;
                uint32_t ah[4], al[4];
                ldm_x4(ah[0], ah[1], ah[2], ah[3], sb + off);
                ldm_x4(al[0], al[1], al[2], al[3], sb + GBUF + off);
#pragma unroll
                for (int j = 0; j < 4; j++) mma16816(acc[i][j], ah, bh[j]);
#pragma unroll
                for (int j = 0; j < 4; j++) mma16816(acc[i][j], ah, bl[j]);
#pragma unroll
                for (int j = 0; j < 4; j++) mma16816(acc[i][j], al, bh[j]);
            }
        }
    }

#pragma unroll
    for (int i = 0; i < 4; i++)
#pragma unroll
        for (int j = 0; j < 4; j++) {
            const int row = by*128 + wm*64 + i*16 + g;
            const int col = bx*128 + wn*32 + j*8 + t4*2;
            float b0 = 0.f, b1 = 0.f;
            if (bias) { b0 = bias[col]; b1 = bias[col + 1]; }
            *(float2*)&C[(size_t)row * ldc + col] =
                make_float2(acc[i][j][0] + b0, acc[i][j][1] + b1);
            *(float2*)&C[(size_t)(row + 8) * ldc + col] =
                make_float2(acc[i][j][2] + b0, acc[i][j][3] + b1);
        }
}

// ---------------------------------------------------------------------------
// RoPE + reshape + bf16 hi/lo split.
// ---------------------------------------------------------------------------
__global__ __launch_bounds__(256) void rope_kernel(
    const float* __restrict__ qkv, const float* __restrict__ pos,
    __nv_bfloat16* __restrict__ qh, __nv_bfloat16* __restrict__ ql,
    __nv_bfloat16* __restrict__ kh, __nv_bfloat16* __restrict__ kl,
    __nv_bfloat16* __restrict__ vTh, __nv_bfloat16* __restrict__ vTl)
{
    const int t0 = blockIdx.x * 128;
    const int bh = blockIdx.y;
    const int b = bh >> 4, h = bh & 15;
    __shared__ float sv[128][65];

    for (int idx = threadIdx.x; idx < 128 * 64; idx += 256) {
        const int t = idx >> 6, d = idx & 63;
        const size_t base = ((size_t)(t0 + t) * 4 + b) * 3072 + h * 64 + d;
        const float qv = qkv[base];
        const float kv = qkv[base + 1024];
        sv[t][d] = qkv[base + 2048];
        float c, s;
        sincosf(pos[(t0 + t) * 64 + d], &s, &c);
        const int po = (d < 32) ? 32 : -32;
        const float rq = (d < 32) ? -qkv[base + po] : qkv[base + po];
        const float rk = (d < 32) ? -qkv[base + 1024 + po] : qkv[base + 1024 + po];
        const float qr = fmaf(qv, c, rq * s) * 0.125f;
        const float kr = fmaf(kv, c, rk * s);
        const size_t o = (size_t)bh * T * D + (size_t)(t0 + t) * 64 + d;
        __nv_bfloat16 hh, ll;
        split_bf(qr, hh, ll); qh[o] = hh; ql[o] = ll;
        split_bf(kr, hh, ll); kh[o] = hh; kl[o] = ll;
    }
    __syncthreads();
    for (int idx = threadIdx.x; idx < 128 * 64; idx += 256) {
        const int d = idx >> 7, t = idx & 127;
        __nv_bfloat16 hh, ll;
        split_bf(sv[t][d], hh, ll);
        const size_t o = ((size_t)bh * 64 + d) * T + t0 + t;
        vTh[o] = hh; vTl[o] = ll;
    }
}

// ---------------------------------------------------------------------------
// Fused attention: S=QK^T -> exp (1/4 FMA-poly, no max) -> attn(unnorm) +
// rowsums + PV -> IN-KERNEL attn normalize (fused rescale) + ctx split-store.
// Double-buffered K/V; one sync per j-tile.
// ---------------------------------------------------------------------------
constexpr int STQ = 72;
constexpr int STV = 136;
constexpr int OQH = 0,  OQL = 18432;
constexpr int OK0 = 36864;                 // + st*36864 (lo at +18432)
constexpr int OV0 = 110592;                // + st*34816 (lo at +17408)
constexpr int FLASH_SMEM = 180224;

__global__ __launch_bounds__(256, 1) void flash_kernel(
    const __nv_bfloat16* __restrict__ qh, const __nv_bfloat16* __restrict__ ql,
    const __nv_bfloat16* __restrict__ kh, const __nv_bfloat16* __restrict__ kl,
    const __nv_bfloat16* __restrict__ vTh, const __nv_bfloat16* __restrict__ vTl,
    float* __restrict__ attn,
    __nv_bfloat16* __restrict__ cxh, __nv_bfloat16* __restrict__ cxl)
{
    const int by = (gridDim.x - 1) - blockIdx.x;   // heavy strips first
    const int bh = blockIdx.y;
    const int b = bh >> 4, h = bh & 15;

    extern __shared__ char smc[];
    const uint32_t su = smem_u32(smc);
    __shared__ float sL[2][128];
    __shared__ float sInv[128];

    const int tid = threadIdx.x, lane = tid & 31, wid = tid >> 5;
    const int wm = wid & 3, wn = wid >> 2;
    const int g = lane >> 2, t4 = lane & 3;
    const int lr16 = lane & 15, kc8 = (lane >> 4) << 3;

    const size_t qoff = (size_t)bh * T * D + (size_t)by * 128 * 64;
    const size_t koff = (size_t)bh * T * D;
    const size_t voff = (size_t)bh * D * T;

    auto issueK = [&](int j, int st) {
        const uint32_t sb = su + OK0 + (uint32_t)st * 36864u;
#pragma unroll
        for (int i = 0; i < 4; i++) {
            const int seg = tid + i * 256;
            const int r = seg >> 3, c = seg & 7;
            const uint32_t so = (uint32_t)(r * STQ + c * 8) * 2u;
            cp16(sb + so,         kh + koff + (size_t)(j*128 + r) * 64 + c * 8);
            cp16(sb + 18432 + so, kl + koff + (size_t)(j*128 + r) * 64 + c * 8);
        }
    };
    auto issueV = [&](int j, int st) {
        const uint32_t vb = su + OV0 + (uint32_t)st * 34816u;
#pragma unroll
        for (int i = 0; i < 4; i++) {
            const int seg = tid + i * 256;
            const int d = seg >> 4, c = seg & 15;
            const uint32_t so = (uint32_t)(d * STV + c * 8) * 2u;
            cp16(vb + so,         vTh + voff + (size_t)d * T + j * 128 + c * 8);
            cp16(vb + 17408 + so, vTl + voff + (size_t)d * T + j * 128 + c * 8);
        }
    };

#pragma unroll
    for (int i = 0; i < 4; i++) {
        const int seg = tid + i * 256;
        const int r = seg >> 3, c = seg & 7;
        const uint32_t so = (uint32_t)(r * STQ + c * 8) * 2u;
        cp16(su + OQH + so, qh + qoff + (size_t)r * 64 + c * 8);
        cp16(su + OQL + so, ql + qoff + (size_t)r * 64 + c * 8);
    }
    issueK(0, 0);
    issueV(0, 0);
    cp_commit();

    float l4[4] = {0.f, 0.f, 0.f, 0.f};
    float cacc[2][8][4] = {};

    for (int j = 0; j <= by; j++) {
        const int st = j & 1;
        cp_wait<0>();
        __syncthreads();
        if (j < by) {
            issueK(j + 1, st ^ 1);
            issueV(j + 1, st ^ 1);
            cp_commit();
        }

        // ---- S = Q Kj^T (bf16x3) ----
        float S[2][8][4] = {};
        const uint32_t kbH = su + OK0 + (uint32_t)st * 36864u;
        const uint32_t kbL = kbH + 18432u;
#pragma unroll
        for (int ks = 0; ks < 4; ks++) {
            const int fk = ks * 16 + kc8;
            uint32_t ah[2][4], al[2][4];
#pragma unroll
            for (int mf = 0; mf < 2; mf++) {
                const uint32_t off = (uint32_t)((wm*32 + mf*16 + lr16) * STQ + fk) * 2u;
                ldm_x4(ah[mf][0], ah[mf][1], ah[mf][2], ah[mf][3], su + OQH + off);
                ldm_x4(al[mf][0], al[mf][1], al[mf][2], al[mf][3], su + OQL + off);
            }
#pragma unroll
            for (int jj = 0; jj < 4; jj++) {
                const uint32_t off = (uint32_t)((wn*64 + jj*16 + lr16) * STQ + fk) * 2u;
                uint32_t bhf[2][2], blf[2][2];
                ldm_x4(bhf[0][0], bhf[1][0], bhf[0][1], bhf[1][1], kbH + off);
                ldm_x4(blf[0][0], blf[1][0], blf[0][1], blf[1][1], kbL + off);
#pragma unroll
                for (int mf = 0; mf < 2; mf++)
#pragma unroll
                    for (int n2 = 0; n2 < 2; n2++)
                        mma16816(S[mf][2*jj + n2], ah[mf], bhf[n2]);
#pragma unroll
                for (int mf = 0; mf < 2; mf++)
#pragma unroll
                    for (int n2 = 0; n2 < 2; n2++)
                        mma16816(S[mf][2*jj + n2], ah[mf], blf[n2]);
#pragma unroll
                for (int mf = 0; mf < 2; mf++)
#pragma unroll
                    for (int n2 = 0; n2 < 2; n2++)
                        mma16816(S[mf][2*jj + n2], al[mf], bhf[n2]);
            }
        }

        // ---- exp (3/4 MUFU, 1/4 FMA poly), mask, l accum, attn store ----
        const int rowbase = by * 128 + wm * 32;
        const int colbase = j * 128 + wn * 64;
        float* ap = attn + (size_t)bh * T * T;
#pragma unroll
        for (int mf = 0; mf < 2; mf++)
#pragma unroll
            for (int nf = 0; nf < 8; nf++) {
                const int row0 = rowbase + mf * 16 + g;
                const int col = colbase + nf * 8 + t4 * 2;
#pragma unroll
                for (int c = 0; c < 4; c++) {
                    const int rr = row0 + ((c >= 2) ? 8 : 0);
                    const int cc = col + (c & 1);
                    float e = (c == 3) ? exp_poly(S[mf][nf][c])
                                       : __expf(S[mf][nf][c]);
                    if (j == by && cc > rr) e = 0.f;
                    S[mf][nf][c] = e;
                    l4[mf * 2 + (c >= 2)] += e;
                }
                *(float2*)&ap[(size_t)row0 * T + col] =
                    make_float2(S[mf][nf][0], S[mf][nf][1]);
                *(float2*)&ap[(size_t)(row0 + 8) * T + col] =
                    make_float2(S[mf][nf][2], S[mf][nf][3]);
            }

        // ---- PV ----
        const uint32_t vbH = su + OV0 + (uint32_t)st * 34816u;
        const uint32_t vbL = vbH + 17408u;
#pragma unroll
        for (int kf = 0; kf < 4; kf++) {
            uint32_t aPh[2][4], aPl[2][4];
#pragma unroll
            for (int mf = 0; mf < 2; mf++) {
                const float* p0 = S[mf][2*kf];
                const float* p1 = S[mf][2*kf + 1];
                __nv_bfloat16 hh[8], ll[8];
                split_bf(p0[0], hh[0], ll[0]); split_bf(p0[1], hh[1], ll[1]);
                split_bf(p0[2], hh[2], ll[2]); split_bf(p0[3], hh[3], ll[3]);
                split_bf(p1[0], hh[4], ll[4]); split_bf(p1[1], hh[5], ll[5]);
                split_bf(p1[2], hh[6], ll[6]); split_bf(p1[3], hh[7], ll[7]);
                aPh[mf][0] = packbf2(hh[0], hh[1]); aPh[mf][1] = packbf2(hh[2], hh[3]);
                aPh[mf][2] = packbf2(hh[4], hh[5]); aPh[mf][3] = packbf2(hh[6], hh[7]);
                aPl[mf][0] = packbf2(ll[0], ll[1]); aPl[mf][1] = packbf2(ll[2], ll[3]);
                aPl[mf][2] = packbf2(ll[4], ll[5]); aPl[mf][3] = packbf2(ll[6], ll[7]);
            }
#pragma unroll
            for (int jj = 0; jj < 4; jj++) {
                const uint32_t off =
                    (uint32_t)((jj*16 + lr16) * STV + wn*64 + kf*16 + kc8) * 2u;
                uint32_t vh[2][2], vl[2][2];
                ldm_x4(vh[0][0], vh[1][0], vh[0][1], vh[1][1], vbH + off);
                ldm_x4(vl[0][0], vl[1][0], vl[0][1], vl[1][1], vbL + off);
#pragma unroll
                for (int mf = 0; mf < 2; mf++)
#pragma unroll
                    for (int n2 = 0; n2 < 2; n2++)
                        mma16816(cacc[mf][2*jj + n2], aPh[mf], vh[n2]);
#pragma unroll
                for (int mf = 0; mf < 2; mf++)
#pragma unroll
                    for (int n2 = 0; n2 < 2; n2++)
                        mma16816(cacc[mf][2*jj + n2], aPh[mf], vl[n2]);
#pragma unroll
                for (int mf = 0; mf < 2; mf++)
#pragma unroll
                    for (int n2 = 0; n2 < 2; n2++)
                        mma16816(cacc[mf][2*jj + n2], aPl[mf], vh[n2]);
            }
        }
    }

    // ---- row sums ----
#pragma unroll
    for (int r4 = 0; r4 < 4; r4++) {
        l4[r4] += __shfl_xor_sync(0xffffffffu, l4[r4], 1);
        l4[r4] += __shfl_xor_sync(0xffffffffu, l4[r4], 2);
    }
    if (t4 == 0) {
#pragma unroll
        for (int mf = 0; mf < 2; mf++)
#pragma unroll
            for (int hf = 0; hf < 2; hf++)
                sL[wn][wm*32 + mf*16 + g + hf*8] = l4[mf*2 + hf];
    }
    __syncthreads();
    if (tid < 128)
        sInv[tid] = 1.f / (sL[0][tid] + sL[1][tid]);

    // ---- zero-fill causal upper region ----
    {
        const int cstart = (by + 1) * 128;
        const int w4 = (T - cstart) >> 2;
        float* ap = attn + (size_t)bh * T * T;
        for (int idx = tid; idx < 128 * w4; idx += 256) {
            const int r = idx / w4, c4 = idx - r * w4;
            *(float4*)&ap[(size_t)(by*128 + r) * T + cstart + c4*4] =
                make_float4(0.f, 0.f, 0.f, 0.f);
        }
    }
    __syncthreads();

    // ---- FUSED rescale: normalize this CTA's 128 attn rows in place ----
    // Rows were just written by this CTA -> high L2 hit probability.
    {
        float* ap = attn + (size_t)bh * T * T + (size_t)by * 128 * T;
        const int w4 = (by + 1) * 32;          // float4s per row
        for (int r = 0; r < 128; r++) {
            const float iv = sInv[r];
            float4* rp = (float4*)(ap + (size_t)r * T);
            for (int c4 = tid; c4 < w4; c4 += 256) {
                float4 v = rp[c4];
                v.x *= iv; v.y *= iv; v.z *= iv; v.w *= iv;
                rp[c4] = v;
            }
        }
    }

    // ---- cross-wn ctx reduce + normalize + split-store ----
    float* sRed = (float*)(smc + OK0);
    if (wn == 1) {
#pragma unroll
        for (int mf = 0; mf < 2; mf++)
#pragma unroll
            for (int nf = 0; nf < 8; nf++) {
                const int lr = wm*32 + mf*16 + g;
                const int col = nf*8 + t4*2;
                sRed[lr*64 + col]       = cacc[mf][nf][0];
                sRed[lr*64 + col + 1]   = cacc[mf][nf][1];
                sRed[(lr+8)*64 + col]   = cacc[mf][nf][2];
                sRed[(lr+8)*64 + col+1] = cacc[mf][nf][3];
            }
    }
    __syncthreads();
    if (wn == 0) {
#pragma unroll
        for (int mf = 0; mf < 2; mf++)
#pragma unroll
            for (int nf = 0; nf < 8; nf++) {
                const int lr = wm*32 + mf*16 + g;
                const int col = nf*8 + t4*2;
                const float iv0 = sInv[lr], iv1 = sInv[lr + 8];
                const float v0 = (cacc[mf][nf][0] + sRed[lr*64 + col])     * iv0;
                const float v1 = (cacc[mf][nf][1] + sRed[lr*64 + col + 1]) * iv0;
                const float v2 = (cacc[mf][nf][2] + sRed[(lr+8)*64 + col])     * iv1;
                const float v3 = (cacc[mf][nf][3] + sRed[(lr+8)*64 + col + 1]) * iv1;
                __nv_bfloat16 h0,h1,h2,h3,l0,l1,l2,l3;
                split_bf(v0,h0,l0); split_bf(v1,h1,l1);
                split_bf(v2,h2,l2); split_bf(v3,h3,l3);
                const size_t o0 = ((size_t)(by*128 + lr)   * 4 + b) * 1024 + h*64 + col;
                const size_t o1 = ((size_t)(by*128 + lr+8) * 4 + b) * 1024 + h*64 + col;
                *(uint32_t*)&cxh[o0] = packbf2(h0, h1);
                *(uint32_t*)&cxl[o0] = packbf2(l0, l1);
                *(uint32_t*)&cxh[o1] = packbf2(h2, h3);
                *(uint32_t*)&cxl[o1] = packbf2(l2, l3);
            }
    }
}

// ---------------------------------------------------------------------------
extern "C" void kernel_launch(void* const* d_in, const int* in_sizes, int n_in,
                              void* d_out, int out_size)
{
    const float* input = (const float*)d_in[0];
    const float* pos   = (const float*)d_in[1];
    const float* in_w  = (const float*)d_in[2];
    const float* in_b  = (const float*)d_in[3];
    const float* out_w = (const float*)d_in[4];
    const float* out_b = (const float*)d_in[5];
    float* out = (float*)d_out;

    float *qkv, *attn_s;
    __nv_bfloat16 *inh, *inl, *wih, *wil, *woh, *wol;
    __nv_bfloat16 *qh, *ql, *kh, *kl, *vTh, *vTl, *cxh, *cxl;
    cudaGetSymbolAddress((void**)&qkv,    g_qkv);
    cudaGetSymbolAddress((void**)&attn_s, g_attn);
    cudaGetSymbolAddress((void**)&inh, g_inh); cudaGetSymbolAddress((void**)&inl, g_inl);
    cudaGetSymbolAddress((void**)&wih, g_wih); cudaGetSymbolAddress((void**)&wil, g_wil);
    cudaGetSymbolAddress((void**)&woh, g_woh); cudaGetSymbolAddress((void**)&wol, g_wol);
    cudaGetSymbolAddress((void**)&qh,  g_qh);  cudaGetSymbolAddress((void**)&ql,  g_ql);
    cudaGetSymbolAddress((void**)&kh,  g_kh);  cudaGetSymbolAddress((void**)&kl,  g_kl);
    cudaGetSymbolAddress((void**)&vTh, g_vTh); cudaGetSymbolAddress((void**)&vTl, g_vTl);
    cudaGetSymbolAddress((void**)&cxh, g_cxh); cudaGetSymbolAddress((void**)&cxl, g_cxl);

    float* attn = ((size_t)out_size >= OUT_ELEMS + ATTN_ELEMS)
                      ? (out + OUT_ELEMS) : attn_s;

    cudaFuncSetAttribute(flash_kernel,
                         cudaFuncAttributeMaxDynamicSharedMemorySize, FLASH_SMEM);
    cudaFuncSetAttribute(gemm_bf,
                         cudaFuncAttributeMaxDynamicSharedMemorySize, GEMM_SMEM);

    // 0) pre-split GEMM operands
    split_kernel<<<(int)(OUT_ELEMS / 2048), 256>>>(input, inh, inl, (int)OUT_ELEMS);
    split_kernel<<<3 * E * E / 2048, 256>>>(in_w, wih, wil, 3 * E * E);
    split_kernel<<<E * E / 2048, 256>>>(out_w, woh, wol, E * E);

    // 1) fused QKV projection (128x128 tiles, 2 CTAs/SM)
    gemm_bf<<<dim3(3 * E / 128, T * B / 128), 256, GEMM_SMEM>>>(
        inh, inl, wih, wil, in_b, qkv, E, 3 * E);

    // 2) RoPE + reshape + bf16 split
    rope_kernel<<<dim3(T / 128, BH), 256>>>(qkv, pos, qh, ql, kh, kl, vTh, vTl);

    // 3) fused attention (scores+exp+PV+normalize, rescale fused in tail)
    flash_kernel<<<dim3(T / 128, BH), 256, FLASH_SMEM>>>(
        qh, ql, kh, kl, vTh, vTl, attn, cxh, cxl);

    // 4) output projection
    gemm_bf<<<dim3(E / 128, T * B / 128), 256, GEMM_SMEM>>>(
        cxh, cxl, woh, wol, out_b, out, E, E);
}

// round 16
// speedup vs baseline: 1.3008x; 1.3008x over previous
#include <cuda_runtime.h>
#include <cuda_bf16.h>
#include <math.h>
#include <stdint.h>

constexpr int T  = 2048;
constexpr int B  = 4;
constexpr int E  = 1024;
constexpr int H  = 16;
constexpr int D  = 64;
constexpr int BH = B * H;

constexpr size_t QKV_ELEMS  = (size_t)T * B * 3 * E;
constexpr size_t HEAD_ELEMS = (size_t)BH * T * D;
constexpr size_t OUT_ELEMS  = (size_t)T * B * E;
constexpr size_t ATTN_ELEMS = (size_t)BH * T * T;

__device__ float g_qkv [QKV_ELEMS];
__device__ float g_attn[ATTN_ELEMS];
__device__ float g_invl[(size_t)BH * T];
__device__ __nv_bfloat16 g_inh[OUT_ELEMS],  g_inl[OUT_ELEMS];
__device__ __nv_bfloat16 g_wih[3*E*E],      g_wil[3*E*E];
__device__ __nv_bfloat16 g_woh[E*E],        g_wol[E*E];
__device__ __nv_bfloat16 g_qh [HEAD_ELEMS], g_ql [HEAD_ELEMS];
__device__ __nv_bfloat16 g_kh [HEAD_ELEMS], g_kl [HEAD_ELEMS];
__device__ __nv_bfloat16 g_vTh[HEAD_ELEMS], g_vTl[HEAD_ELEMS];
__device__ __nv_bfloat16 g_cxh[OUT_ELEMS],  g_cxl[OUT_ELEMS];

// ---------------------------------------------------------------------------
__device__ __forceinline__ uint32_t smem_u32(const void* p) {
    uint32_t a;
    asm("{ .reg .u64 t; cvta.to.shared.u64 t, %1; cvt.u32.u64 %0, t; }"
        : "=r"(a) : "l"(p));
    return a;
}
__device__ __forceinline__ void ldm_x4(uint32_t& r0, uint32_t& r1,
                                       uint32_t& r2, uint32_t& r3, uint32_t addr) {
    asm volatile("ldmatrix.sync.aligned.m8n8.x4.shared.b16 {%0,%1,%2,%3}, [%4];"
                 : "=r"(r0), "=r"(r1), "=r"(r2), "=r"(r3) : "r"(addr));
}
__device__ __forceinline__ void mma16816(float* c, const uint32_t* a,
                                         const uint32_t* b) {
    asm volatile(
        "mma.sync.aligned.m16n8k16.row.col.f32.bf16.bf16.f32 "
        "{%0,%1,%2,%3}, {%4,%5,%6,%7}, {%8,%9}, {%0,%1,%2,%3};"
        : "+f"(c[0]), "+f"(c[1]), "+f"(c[2]), "+f"(c[3])
        : "r"(a[0]), "r"(a[1]), "r"(a[2]), "r"(a[3]), "r"(b[0]), "r"(b[1]));
}
__device__ __forceinline__ void cp16(uint32_t dst, const void* src) {
    asm volatile("cp.async.cg.shared.global [%0], [%1], 16;" :: "r"(dst), "l"(src));
}
__device__ __forceinline__ void cp_commit() { asm volatile("cp.async.commit_group;"); }
template<int N> __device__ __forceinline__ void cp_wait() {
    asm volatile("cp.async.wait_group %0;" :: "n"(N));
}
__device__ __forceinline__ uint32_t packbf2(__nv_bfloat16 a, __nv_bfloat16 b) {
    __nv_bfloat162 t(a, b);
    return *reinterpret_cast<uint32_t*>(&t);
}
__device__ __forceinline__ void split_bf(float x, __nv_bfloat16& h, __nv_bfloat16& l) {
    h = __float2bfloat16(x);
    l = __float2bfloat16(x - __bfloat162float(h));
}
// exp via FMA/ALU pipes (offload from MUFU). Valid |s| <~ 80; rel err ~3e-6.
__device__ __forceinline__ float exp_poly(float s) {
    const float y = s * 1.4426950408889634f;   // log2(e)
    const float r = rintf(y);
    const float f = y - r;
    const int   i = (int)r;
    float p = 0.00133335581f;
    p = fmaf(p, f, 0.00961812911f);
    p = fmaf(p, f, 0.0555041087f);
    p = fmaf(p, f, 0.240226507f);
    p = fmaf(p, f, 0.693147180f);
    p = fmaf(p, f, 1.0f);
    return p * __int_as_float((i + 127) << 23);
}

// ---------------------------------------------------------------------------
// Split fp32 -> bf16 hi/lo
// ---------------------------------------------------------------------------
__global__ __launch_bounds__(256) void split_kernel(
    const float* __restrict__ src, __nv_bfloat16* __restrict__ dh,
    __nv_bfloat16* __restrict__ dl, int n)
{
    int i = blockIdx.x * 2048 + threadIdx.x;
#pragma unroll
    for (int k = 0; k < 8; k++, i += 256) {
        if (i < n) {
            __nv_bfloat16 h, l;
            split_bf(src[i], h, l);
            dh[i] = h; dl[i] = l;
        }
    }
}

// ---------------------------------------------------------------------------
// GEMM (TN) on pre-split bf16:  C = A @ B^T (+bias).
// 128x64 tile, 256 threads (8 warps 2m x 4n, warp 64x16), K-chunk 32,
// 2-stage cp.async, one sync per chunk. 3 CTAs/SM target.
// ---------------------------------------------------------------------------
constexpr int GST = 40;
constexpr int GABUF = 128 * GST * 2;         // 10240 B (A hi or lo)
constexpr int GBBUF = 64 * GST * 2;          //  5120 B (B hi or lo)
constexpr int GSTAGE = 2 * GABUF + 2 * GBBUF;  // 30720 B per stage
constexpr int GEMM_SMEM = 2 * GSTAGE;          // 61440 B

__global__ __launch_bounds__(256, 3) void gemm_bf(
    const __nv_bfloat16* __restrict__ Ah, const __nv_bfloat16* __restrict__ Al,
    const __nv_bfloat16* __restrict__ Bh, const __nv_bfloat16* __restrict__ Bl,
    const float* __restrict__ bias, float* __restrict__ C, int K, int ldc)
{
    const int bx = blockIdx.x, by = blockIdx.y;
    extern __shared__ char sm[];
    const uint32_t su = smem_u32(sm);

    const int tid = threadIdx.x, lane = tid & 31, wid = tid >> 5;
    const int wm = wid & 1, wn = wid >> 1;          // 2m x 4n (warp 64x16)
    const int lr16 = lane & 15, kc8 = (lane >> 4) << 3;
    const int g = lane >> 2, t4 = lane & 3;

    const __nv_bfloat16* gAh = Ah + (size_t)(by * 128) * K;
    const __nv_bfloat16* gAl = Al + (size_t)(by * 128) * K;
    const __nv_bfloat16* gBh = Bh + (size_t)(bx * 64) * K;
    const __nv_bfloat16* gBl = Bl + (size_t)(bx * 64) * K;

    auto issue = [&](int ch, int s) {
        const uint32_t sb = su + (uint32_t)s * GSTAGE;
        const int k0 = ch * 32;
#pragma unroll
        for (int i = 0; i < 2; i++) {                // A: 512 segs each array
            const int seg = tid + i * 256;
            const int r = seg >> 2, c = seg & 3;
            const uint32_t so = (uint32_t)(r * GST + c * 8) * 2u;
            const size_t go = (size_t)r * K + k0 + c * 8;
            cp16(sb + so,          gAh + go);
            cp16(sb + GABUF + so,  gAl + go);
        }
        {                                            // B: 256 segs each array
            const int r = tid >> 2, c = tid & 3;
            const uint32_t so = (uint32_t)(r * GST + c * 8) * 2u;
            const size_t go = (size_t)r * K + k0 + c * 8;
            cp16(sb + 2*GABUF + so,          gBh + go);
            cp16(sb + 2*GABUF + GBBUF + so,  gBl + go);
        }
        cp_commit();
    };

    float acc[4][2][4] = {};
    const int nch = K >> 5;
    issue(0, 0);

    for (int ch = 0; ch < nch; ch++) {
        cp_wait<0>();
        __syncthreads();
        if (ch + 1 < nch) issue(ch + 1, (ch + 1) & 1);

        const uint32_t sb = su + (uint32_t)(ch & 1) * GSTAGE;
#pragma unroll
        for (int ks = 0; ks < 2; ks++) {
            const int fk = ks * 16 + kc8;
            uint32_t bh[2][2], bl[2][2];
            {
                const uint32_t off = (uint32_t)((wn*16 + lr16) * GST + fk) * 2u;
                ldm_x4(bh[0][0], bh[1][0], bh[0][1], bh[1][1],
                       sb + 2*GABUF + off);
                ldm_x4(bl[0][0], bl[1][0], bl[0][1], bl[1][1],
                       sb + 2*GABUF + GBBUF + off);
            }
#pragma unroll
            for (int i = 0; i < 4; i++) {
                const uint32_t off = (uint32_t)((wm*64 + i*16 + lr16) * GST + fk) * 2u;
                uint32_t ah[4], al[4];
                ldm_x4(ah[0], ah[1], ah[2], ah[3], sb + off);
                ldm_x4(al[0], al[1], al[2], al[3], sb + GABUF + off);
#pragma unroll
                for (int j = 0; j < 2; j++) mma16816(acc[i][j], ah, bh[j]);
#pragma unroll
                for (int j = 0; j < 2; j++) mma16816(acc[i][j], ah, bl[j]);
#pragma unroll
                for (int j = 0; j < 2; j++) mma16816(acc[i][j], al, bh[j]);
            }
        }
    }

#pragma unroll
    for (int i = 0; i < 4; i++)
#pragma unroll
        for (int j = 0; j < 2; j++) {
            const int row = by*128 + wm*64 + i*16 + g;
            const int col = bx*64 + wn*16 + j*8 + t4*2;
            float b0 = 0.f, b1 = 0.f;
            if (bias) { b0 = bias[col]; b1 = bias[col + 1]; }
            *(float2*)&C[(size_t)row * ldc + col] =
                make_float2(acc[i][j][0] + b0, acc[i][j][1] + b1);
            *(float2*)&C[(size_t)(row + 8) * ldc + col] =
                make_float2(acc[i][j][2] + b0, acc[i][j][3] + b1);
        }
}

// ---------------------------------------------------------------------------
// RoPE + reshape + bf16 hi/lo split.
// ---------------------------------------------------------------------------
__global__ __launch_bounds__(256) void rope_kernel(
    const float* __restrict__ qkv, const float* __restrict__ pos,
    __nv_bfloat16* __restrict__ qh, __nv_bfloat16* __restrict__ ql,
    __nv_bfloat16* __restrict__ kh, __nv_bfloat16* __restrict__ kl,
    __nv_bfloat16* __restrict__ vTh, __nv_bfloat16* __restrict__ vTl)
{
    const int t0 = blockIdx.x * 128;
    const int bh = blockIdx.y;
    const int b = bh >> 4, h = bh & 15;
    __shared__ float sv[128][65];

    for (int idx = threadIdx.x; idx < 128 * 64; idx += 256) {
        const int t = idx >> 6, d = idx & 63;
        const size_t base = ((size_t)(t0 + t) * 4 + b) * 3072 + h * 64 + d;
        const float qv = qkv[base];
        const float kv = qkv[base + 1024];
        sv[t][d] = qkv[base + 2048];
        float c, s;
        sincosf(pos[(t0 + t) * 64 + d], &s, &c);
        const int po = (d < 32) ? 32 : -32;
        const float rq = (d < 32) ? -qkv[base + po] : qkv[base + po];
        const float rk = (d < 32) ? -qkv[base + 1024 + po] : qkv[base + 1024 + po];
        const float qr = fmaf(qv, c, rq * s) * 0.125f;
        const float kr = fmaf(kv, c, rk * s);
        const size_t o = (size_t)bh * T * D + (size_t)(t0 + t) * 64 + d;
        __nv_bfloat16 hh, ll;
        split_bf(qr, hh, ll); qh[o] = hh; ql[o] = ll;
        split_bf(kr, hh, ll); kh[o] = hh; kl[o] = ll;
    }
    __syncthreads();
    for (int idx = threadIdx.x; idx < 128 * 64; idx += 256) {
        const int d = idx >> 7, t = idx & 127;
        __nv_bfloat16 hh, ll;
        split_bf(sv[t][d], hh, ll);
        const size_t o = ((size_t)bh * 64 + d) * T + t0 + t;
        vTh[o] = hh; vTl[o] = ll;
    }
}

// ---------------------------------------------------------------------------
// Fused attention: S=QK^T -> exp (3/4 MUFU, 1/4 FMA-poly; no max) ->
// attn(unnorm) + rowsums + PV. Double-buffered K/V; one sync per j-tile.
// ---------------------------------------------------------------------------
constexpr int STQ = 72;
constexpr int STV = 136;
constexpr int OQH = 0,  OQL = 18432;
constexpr int OK0 = 36864;                 // + st*36864 (lo at +18432)
constexpr int OV0 = 110592;                // + st*34816 (lo at +17408)
constexpr int FLASH_SMEM = 180224;

__global__ __launch_bounds__(256, 1) void flash_kernel(
    const __nv_bfloat16* __restrict__ qh, const __nv_bfloat16* __restrict__ ql,
    const __nv_bfloat16* __restrict__ kh, const __nv_bfloat16* __restrict__ kl,
    const __nv_bfloat16* __restrict__ vTh, const __nv_bfloat16* __restrict__ vTl,
    float* __restrict__ attn, float* __restrict__ invl_g,
    __nv_bfloat16* __restrict__ cxh, __nv_bfloat16* __restrict__ cxl)
{
    const int by = (gridDim.x - 1) - blockIdx.x;
    const int bh = blockIdx.y;
    const int b = bh >> 4, h = bh & 15;

    extern __shared__ char smc[];
    const uint32_t su = smem_u32(smc);
    __shared__ float sL[2][128];
    __shared__ float sInv[128];

    const int tid = threadIdx.x, lane = tid & 31, wid = tid >> 5;
    const int wm = wid & 3, wn = wid >> 2;
    const int g = lane >> 2, t4 = lane & 3;
    const int lr16 = lane & 15, kc8 = (lane >> 4) << 3;

    const size_t qoff = (size_t)bh * T * D + (size_t)by * 128 * 64;
    const size_t koff = (size_t)bh * T * D;
    const size_t voff = (size_t)bh * D * T;

    auto issueK = [&](int j, int st) {
        const uint32_t sb = su + OK0 + (uint32_t)st * 36864u;
#pragma unroll
        for (int i = 0; i < 4; i++) {
            const int seg = tid + i * 256;
            const int r = seg >> 3, c = seg & 7;
            const uint32_t so = (uint32_t)(r * STQ + c * 8) * 2u;
            cp16(sb + so,         kh + koff + (size_t)(j*128 + r) * 64 + c * 8);
            cp16(sb + 18432 + so, kl + koff + (size_t)(j*128 + r) * 64 + c * 8);
        }
    };
    auto issueV = [&](int j, int st) {
        const uint32_t vb = su + OV0 + (uint32_t)st * 34816u;
#pragma unroll
        for (int i = 0; i < 4; i++) {
            const int seg = tid + i * 256;
            const int d = seg >> 4, c = seg & 15;
            const uint32_t so = (uint32_t)(d * STV + c * 8) * 2u;
            cp16(vb + so,         vTh + voff + (size_t)d * T + j * 128 + c * 8);
            cp16(vb + 17408 + so, vTl + voff + (size_t)d * T + j * 128 + c * 8);
        }
    };

#pragma unroll
    for (int i = 0; i < 4; i++) {
        const int seg = tid + i * 256;
        const int r = seg >> 3, c = seg & 7;
        const uint32_t so = (uint32_t)(r * STQ + c * 8) * 2u;
        cp16(su + OQH + so, qh + qoff + (size_t)r * 64 + c * 8);
        cp16(su + OQL + so, ql + qoff + (size_t)r * 64 + c * 8);
    }
    issueK(0, 0);
    issueV(0, 0);
    cp_commit();

    float l4[4] = {0.f, 0.f, 0.f, 0.f};
    float cacc[2][8][4] = {};

    for (int j = 0; j <= by; j++) {
        const int st = j & 1;
        cp_wait<0>();
        __syncthreads();
        if (j < by) {
            issueK(j + 1, st ^ 1);
            issueV(j + 1, st ^ 1);
            cp_commit();
        }

        // ---- S = Q Kj^T (bf16x3) ----
        float S[2][8][4] = {};
        const uint32_t kbH = su + OK0 + (uint32_t)st * 36864u;
        const uint32_t kbL = kbH + 18432u;
#pragma unroll
        for (int ks = 0; ks < 4; ks++) {
            const int fk = ks * 16 + kc8;
            uint32_t ah[2][4], al[2][4];
#pragma unroll
            for (int mf = 0; mf < 2; mf++) {
                const uint32_t off = (uint32_t)((wm*32 + mf*16 + lr16) * STQ + fk) * 2u;
                ldm_x4(ah[mf][0], ah[mf][1], ah[mf][2], ah[mf][3], su + OQH + off);
                ldm_x4(al[mf][0], al[mf][1], al[mf][2], al[mf][3], su + OQL + off);
            }
#pragma unroll
            for (int jj = 0; jj < 4; jj++) {
                const uint32_t off = (uint32_t)((wn*64 + jj*16 + lr16) * STQ + fk) * 2u;
                uint32_t bhf[2][2], blf[2][2];
                ldm_x4(bhf[0][0], bhf[1][0], bhf[0][1], bhf[1][1], kbH + off);
                ldm_x4(blf[0][0], blf[1][0], blf[0][1], blf[1][1], kbL + off);
#pragma unroll
                for (int mf = 0; mf < 2; mf++)
#pragma unroll
                    for (int n2 = 0; n2 < 2; n2++)
                        mma16816(S[mf][2*jj + n2], ah[mf], bhf[n2]);
#pragma unroll
                for (int mf = 0; mf < 2; mf++)
#pragma unroll
                    for (int n2 = 0; n2 < 2; n2++)
                        mma16816(S[mf][2*jj + n2], ah[mf], blf[n2]);
#pragma unroll
                for (int mf = 0; mf < 2; mf++)
#pragma unroll
                    for (int n2 = 0; n2 < 2; n2++)
                        mma16816(S[mf][2*jj + n2], al[mf], bhf[n2]);
            }
        }

        // ---- exp (3/4 MUFU, 1/4 FMA poly), mask, l accum, attn store ----
        const int rowbase = by * 128 + wm * 32;
        const int colbase = j * 128 + wn * 64;
        float* ap = attn + (size_t)bh * T * T;
#pragma unroll
        for (int mf = 0; mf < 2; mf++)
#pragma unroll
            for (int nf = 0; nf < 8; nf++) {
                const int row0 = rowbase + mf * 16 + g;
                const int col = colbase + nf * 8 + t4 * 2;
#pragma unroll
                for (int c = 0; c < 4; c++) {
                    const int rr = row0 + ((c >= 2) ? 8 : 0);
                    const int cc = col + (c & 1);
                    float e = (c == 3) ? exp_poly(S[mf][nf][c])
                                       : __expf(S[mf][nf][c]);
                    if (j == by && cc > rr) e = 0.f;
                    S[mf][nf][c] = e;
                    l4[mf * 2 + (c >= 2)] += e;
                }
                *(float2*)&ap[(size_t)row0 * T + col] =
                    make_float2(S[mf][nf][0], S[mf][nf][1]);
                *(float2*)&ap[(size_t)(row0 + 8) * T + col] =
                    make_float2(S[mf][nf][2], S[mf][nf][3]);
            }

        // ---- PV ----
        const uint32_t vbH = su + OV0 + (uint32_t)st * 34816u;
        const uint32_t vbL = vbH + 17408u;
#pragma unroll
        for (int kf = 0; kf < 4; kf++) {
            uint32_t aPh[2][4], aPl[2][4];
#pragma unroll
            for (int mf = 0; mf < 2; mf++) {
                const float* p0 = S[mf][2*kf];
                const float* p1 = S[mf][2*kf + 1];
                __nv_bfloat16 hh[8], ll[8];
                split_bf(p0[0], hh[0], ll[0]); split_bf(p0[1], hh[1], ll[1]);
                split_bf(p0[2], hh[2], ll[2]); split_bf(p0[3], hh[3], ll[3]);
                split_bf(p1[0], hh[4], ll[4]); split_bf(p1[1], hh[5], ll[5]);
                split_bf(p1[2], hh[6], ll[6]); split_bf(p1[3], hh[7], ll[7]);
                aPh[mf][0] = packbf2(hh[0], hh[1]); aPh[mf][1] = packbf2(hh[2], hh[3]);
                aPh[mf][2] = packbf2(hh[4], hh[5]); aPh[mf][3] = packbf2(hh[6], hh[7]);
                aPl[mf][0] = packbf2(ll[0], ll[1]); aPl[mf][1] = packbf2(ll[2], ll[3]);
                aPl[mf][2] = packbf2(ll[4], ll[5]); aPl[mf][3] = packbf2(ll[6], ll[7]);
            }
#pragma unroll
            for (int jj = 0; jj < 4; jj++) {
                const uint32_t off =
                    (uint32_t)((jj*16 + lr16) * STV + wn*64 + kf*16 + kc8) * 2u;
                uint32_t vh[2][2], vl[2][2];
                ldm_x4(vh[0][0], vh[1][0], vh[0][1], vh[1][1], vbH + off);
                ldm_x4(vl[0][0], vl[1][0], vl[0][1], vl[1][1], vbL + off);
#pragma unroll
                for (int mf = 0; mf < 2; mf++)
#pragma unroll
                    for (int n2 = 0; n2 < 2; n2++)
                        mma16816(cacc[mf][2*jj + n2], aPh[mf], vh[n2]);
#pragma unroll
                for (int mf = 0; mf < 2; mf++)
#pragma unroll
                    for (int n2 = 0; n2 < 2; n2++)
                        mma16816(cacc[mf][2*jj + n2], aPh[mf], vl[n2]);
#pragma unroll
                for (int mf = 0; mf < 2; mf++)
#pragma unroll
                    for (int n2 = 0; n2 < 2; n2++)
                        mma16816(cacc[mf][2*jj + n2], aPl[mf], vh[n2]);
            }
        }
    }

    // ---- row sums ----
#pragma unroll
    for (int r4 = 0; r4 < 4; r4++) {
        l4[r4] += __shfl_xor_sync(0xffffffffu, l4[r4], 1);
        l4[r4] += __shfl_xor_sync(0xffffffffu, l4[r4], 2);
    }
    if (t4 == 0) {
#pragma unroll
        for (int mf = 0; mf < 2; mf++)
#pragma unroll
            for (int hf = 0; hf < 2; hf++)
                sL[wn][wm*32 + mf*16 + g + hf*8] = l4[mf*2 + hf];
    }
    __syncthreads();
    if (tid < 128) {
        const float iv = 1.f / (sL[0][tid] + sL[1][tid]);
        sInv[tid] = iv;
        invl_g[(size_t)bh * T + by * 128 + tid] = iv;
    }

    // ---- zero-fill causal upper region ----
    {
        const int cstart = (by + 1) * 128;
        const int w4 = (T - cstart) >> 2;
        float* ap = attn + (size_t)bh * T * T;
        for (int idx = tid; idx < 128 * w4; idx += 256) {
            const int r = idx / w4, c4 = idx - r * w4;
            *(float4*)&ap[(size_t)(by*128 + r) * T + cstart + c4*4] =
                make_float4(0.f, 0.f, 0.f, 0.f);
        }
    }
    __syncthreads();

    // ---- cross-wn ctx reduce + normalize + split-store ----
    float* sRed = (float*)(smc + OK0);
    if (wn == 1) {
#pragma unroll
        for (int mf = 0; mf < 2; mf++)
#pragma unroll
            for (int nf = 0; nf < 8; nf++) {
                const int lr = wm*32 + mf*16 + g;
                const int col = nf*8 + t4*2;
                sRed[lr*64 + col]       = cacc[mf][nf][0];
                sRed[lr*64 + col + 1]   = cacc[mf][nf][1];
                sRed[(lr+8)*64 + col]   = cacc[mf][nf][2];
                sRed[(lr+8)*64 + col+1] = cacc[mf][nf][3];
            }
    }
    __syncthreads();
    if (wn == 0) {
#pragma unroll
        for (int mf = 0; mf < 2; mf++)
#pragma unroll
            for (int nf = 0; nf < 8; nf++) {
                const int lr = wm*32 + mf*16 + g;
                const int col = nf*8 + t4*2;
                const float iv0 = sInv[lr], iv1 = sInv[lr + 8];
                const float v0 = (cacc[mf][nf][0] + sRed[lr*64 + col])     * iv0;
                const float v1 = (cacc[mf][nf][1] + sRed[lr*64 + col + 1]) * iv0;
                const float v2 = (cacc[mf][nf][2] + sRed[(lr+8)*64 + col])     * iv1;
                const float v3 = (cacc[mf][nf][3] + sRed[(lr+8)*64 + col + 1]) * iv1;
                __nv_bfloat16 h0,h1,h2,h3,l0,l1,l2,l3;
                split_bf(v0,h0,l0); split_bf(v1,h1,l1);
                split_bf(v2,h2,l2); split_bf(v3,h3,l3);
                const size_t o0 = ((size_t)(by*128 + lr)   * 4 + b) * 1024 + h*64 + col;
                const size_t o1 = ((size_t)(by*128 + lr+8) * 4 + b) * 1024 + h*64 + col;
                *(uint32_t*)&cxh[o0] = packbf2(h0, h1);
                *(uint32_t*)&cxl[o0] = packbf2(l0, l1);
                *(uint32_t*)&cxh[o1] = packbf2(h2, h3);
                *(uint32_t*)&cxl[o1] = packbf2(l2, l3);
            }
    }
}

// ---------------------------------------------------------------------------
// Rescale: attn[bh][t][0..t] *= invl[bh][t].  8 rows per block (R12 form).
// ---------------------------------------------------------------------------
__global__ __launch_bounds__(256) void rescale_kernel(
    float* __restrict__ attn, const float* __restrict__ invl)
{
    const int bh = blockIdx.y;
    const int t0 = blockIdx.x * 8;
#pragma unroll
    for (int r = 0; r < 8; r++) {
        const int t = t0 + r;
        const float iv = invl[(size_t)bh * T + t];
        float* rowp = attn + (size_t)bh * T * T + (size_t)t * T;
        const int L = t + 1;
        const int n4 = L >> 2;
        float4* r4 = (float4*)rowp;
        for (int i = threadIdx.x; i < n4; i += 256) {
            float4 v = r4[i];
            v.x *= iv; v.y *= iv; v.z *= iv; v.w *= iv;
            r4[i] = v;
        }
        const int tail = n4 * 4 + threadIdx.x;
        if (tail < L) rowp[tail] *= iv;
    }
}

// ---------------------------------------------------------------------------
extern "C" void kernel_launch(void* const* d_in, const int* in_sizes, int n_in,
                              void* d_out, int out_size)
{
    const float* input = (const float*)d_in[0];
    const float* pos   = (const float*)d_in[1];
    const float* in_w  = (const float*)d_in[2];
    const float* in_b  = (const float*)d_in[3];
    const float* out_w = (const float*)d_in[4];
    const float* out_b = (const float*)d_in[5];
    float* out = (float*)d_out;

    float *qkv, *attn_s, *invl;
    __nv_bfloat16 *inh, *inl, *wih, *wil, *woh, *wol;
    __nv_bfloat16 *qh, *ql, *kh, *kl, *vTh, *vTl, *cxh, *cxl;
    cudaGetSymbolAddress((void**)&qkv,    g_qkv);
    cudaGetSymbolAddress((void**)&attn_s, g_attn);
    cudaGetSymbolAddress((void**)&invl,   g_invl);
    cudaGetSymbolAddress((void**)&inh, g_inh); cudaGetSymbolAddress((void**)&inl, g_inl);
    cudaGetSymbolAddress((void**)&wih, g_wih); cudaGetSymbolAddress((void**)&wil, g_wil);
    cudaGetSymbolAddress((void**)&woh, g_woh); cudaGetSymbolAddress((void**)&wol, g_wol);
    cudaGetSymbolAddress((void**)&qh,  g_qh);  cudaGetSymbolAddress((void**)&ql,  g_ql);
    cudaGetSymbolAddress((void**)&kh,  g_kh);  cudaGetSymbolAddress((void**)&kl,  g_kl);
    cudaGetSymbolAddress((void**)&vTh, g_vTh); cudaGetSymbolAddress((void**)&vTl, g_vTl);
    cudaGetSymbolAddress((void**)&cxh, g_cxh); cudaGetSymbolAddress((void**)&cxl, g_cxl);

    float* attn = ((size_t)out_size >= OUT_ELEMS + ATTN_ELEMS)
                      ? (out + OUT_ELEMS) : attn_s;

    cudaFuncSetAttribute(flash_kernel,
                         cudaFuncAttributeMaxDynamicSharedMemorySize, FLASH_SMEM);
    cudaFuncSetAttribute(gemm_bf,
                         cudaFuncAttributeMaxDynamicSharedMemorySize, GEMM_SMEM);

    // 0) pre-split GEMM operands
    split_kernel<<<(int)(OUT_ELEMS / 2048), 256>>>(input, inh, inl, (int)OUT_ELEMS);
    split_kernel<<<3 * E * E / 2048, 256>>>(in_w, wih, wil, 3 * E * E);
    split_kernel<<<E * E / 2048, 256>>>(out_w, woh, wol, E * E);

    // 1) fused QKV projection (128x64 tiles, 3 CTAs/SM)
    gemm_bf<<<dim3(3 * E / 64, T * B / 128), 256, GEMM_SMEM>>>(
        inh, inl, wih, wil, in_b, qkv, E, 3 * E);

    // 2) RoPE + reshape + bf16 split
    rope_kernel<<<dim3(T / 128, BH), 256>>>(qkv, pos, qh, ql, kh, kl, vTh, vTl);

    // 3) fused attention (1/4 poly exp)
    flash_kernel<<<dim3(T / 128, BH), 256, FLASH_SMEM>>>(
        qh, ql, kh, kl, vTh, vTl, attn, invl, cxh, cxl);

    // 4) normalize attn rows
    rescale_kernel<<<dim3(T / 8, BH), 256>>>(attn, invl);

    // 5) output projection
    gemm_bf<<<dim3(E / 64, T * B / 128), 256, GEMM_SMEM>>>(
        cxh, cxl, woh, wol, out_b, out, E, E);
}

// round 17
// speedup vs baseline: 1.3510x; 1.0386x over previous
#include <cuda_runtime.h>
#include <cuda_bf16.h>
#include <math.h>
#include <stdint.h>

constexpr int T  = 2048;
constexpr int B  = 4;
constexpr int E  = 1024;
constexpr int H  = 16;
constexpr int D  = 64;
constexpr int BH = B * H;

constexpr size_t QKV_ELEMS  = (size_t)T * B * 3 * E;
constexpr size_t HEAD_ELEMS = (size_t)BH * T * D;
constexpr size_t OUT_ELEMS  = (size_t)T * B * E;
constexpr size_t ATTN_ELEMS = (size_t)BH * T * T;

__device__ float g_qkv [QKV_ELEMS];
__device__ float g_attn[ATTN_ELEMS];
__device__ float g_invl[(size_t)BH * T];
__device__ __nv_bfloat16 g_inh[OUT_ELEMS],  g_inl[OUT_ELEMS];
__device__ __nv_bfloat16 g_wih[3*E*E],      g_wil[3*E*E];
__device__ __nv_bfloat16 g_woh[E*E],        g_wol[E*E];
__device__ __nv_bfloat16 g_qh [HEAD_ELEMS], g_ql [HEAD_ELEMS];
__device__ __nv_bfloat16 g_kh [HEAD_ELEMS], g_kl [HEAD_ELEMS];
__device__ __nv_bfloat16 g_vTh[HEAD_ELEMS], g_vTl[HEAD_ELEMS];
__device__ __nv_bfloat16 g_cxh[OUT_ELEMS],  g_cxl[OUT_ELEMS];

// ---------------------------------------------------------------------------
__device__ __forceinline__ uint32_t smem_u32(const void* p) {
    uint32_t a;
    asm("{ .reg .u64 t; cvta.to.shared.u64 t, %1; cvt.u32.u64 %0, t; }"
        : "=r"(a) : "l"(p));
    return a;
}
__device__ __forceinline__ void ldm_x4(uint32_t& r0, uint32_t& r1,
                                       uint32_t& r2, uint32_t& r3, uint32_t addr) {
    asm volatile("ldmatrix.sync.aligned.m8n8.x4.shared.b16 {%0,%1,%2,%3}, [%4];"
                 : "=r"(r0), "=r"(r1), "=r"(r2), "=r"(r3) : "r"(addr));
}
__device__ __forceinline__ void mma16816(float* c, const uint32_t* a,
                                         const uint32_t* b) {
    asm volatile(
        "mma.sync.aligned.m16n8k16.row.col.f32.bf16.bf16.f32 "
        "{%0,%1,%2,%3}, {%4,%5,%6,%7}, {%8,%9}, {%0,%1,%2,%3};"
        : "+f"(c[0]), "+f"(c[1]), "+f"(c[2]), "+f"(c[3])
        : "r"(a[0]), "r"(a[1]), "r"(a[2]), "r"(a[3]), "r"(b[0]), "r"(b[1]));
}
__device__ __forceinline__ void cp16(uint32_t dst, const void* src) {
    asm volatile("cp.async.cg.shared.global [%0], [%1], 16;" :: "r"(dst), "l"(src));
}
__device__ __forceinline__ void cp_commit() { asm volatile("cp.async.commit_group;"); }
template<int N> __device__ __forceinline__ void cp_wait() {
    asm volatile("cp.async.wait_group %0;" :: "n"(N));
}
__device__ __forceinline__ uint32_t packbf2(__nv_bfloat16 a, __nv_bfloat16 b) {
    __nv_bfloat162 t(a, b);
    return *reinterpret_cast<uint32_t*>(&t);
}
__device__ __forceinline__ void split_bf(float x, __nv_bfloat16& h, __nv_bfloat16& l) {
    h = __float2bfloat16(x);
    l = __float2bfloat16(x - __bfloat162float(h));
}
// exp via FMA/ALU pipes (offload from MUFU). Valid |s| <~ 80; rel err ~3e-6.
__device__ __forceinline__ float exp_poly(float s) {
    const float y = s * 1.4426950408889634f;   // log2(e)
    const float r = rintf(y);
    const float f = y - r;
    const int   i = (int)r;
    float p = 0.00133335581f;
    p = fmaf(p, f, 0.00961812911f);
    p = fmaf(p, f, 0.0555041087f);
    p = fmaf(p, f, 0.240226507f);
    p = fmaf(p, f, 0.693147180f);
    p = fmaf(p, f, 1.0f);
    return p * __int_as_float((i + 127) << 23);
}

// ---------------------------------------------------------------------------
// Split fp32 -> bf16 hi/lo
// ---------------------------------------------------------------------------
__global__ __launch_bounds__(256) void split_kernel(
    const float* __restrict__ src, __nv_bfloat16* __restrict__ dh,
    __nv_bfloat16* __restrict__ dl, int n)
{
    int i = blockIdx.x * 2048 + threadIdx.x;
#pragma unroll
    for (int k = 0; k < 8; k++, i += 256) {
        if (i < n) {
            __nv_bfloat16 h, l;
            split_bf(src[i], h, l);
            dh[i] = h; dl[i] = l;
        }
    }
}

// ---------------------------------------------------------------------------
// GEMM (TN) on pre-split bf16:  C = A @ B^T (+bias).  (R12 config)
// 128x128 tile, 256 threads (8 warps 2m x 4n), K-chunk 32, 2-stage cp.async.
// ---------------------------------------------------------------------------
constexpr int GST = 40;
constexpr int GBUF = 128 * GST * 2;          // 10240 B
constexpr int GSTAGE = 4 * GBUF;             // 40960 B
constexpr int GEMM_SMEM = 2 * GSTAGE;        // 81920 B

__global__ __launch_bounds__(256) void gemm_bf(
    const __nv_bfloat16* __restrict__ Ah, const __nv_bfloat16* __restrict__ Al,
    const __nv_bfloat16* __restrict__ Bh, const __nv_bfloat16* __restrict__ Bl,
    const float* __restrict__ bias, float* __restrict__ C, int K, int ldc)
{
    const int bx = blockIdx.x, by = blockIdx.y;
    extern __shared__ char sm[];
    const uint32_t su = smem_u32(sm);

    const int tid = threadIdx.x, lane = tid & 31, wid = tid >> 5;
    const int wm = wid & 1, wn = wid >> 1;
    const int lr16 = lane & 15, kc8 = (lane >> 4) << 3;
    const int g = lane >> 2, t4 = lane & 3;

    const __nv_bfloat16* gAh = Ah + (size_t)(by * 128) * K;
    const __nv_bfloat16* gAl = Al + (size_t)(by * 128) * K;
    const __nv_bfloat16* gBh = Bh + (size_t)(bx * 128) * K;
    const __nv_bfloat16* gBl = Bl + (size_t)(bx * 128) * K;

    auto issue = [&](int ch, int s) {
        const uint32_t sb = su + (uint32_t)s * GSTAGE;
        const int k0 = ch * 32;
#pragma unroll
        for (int i = 0; i < 2; i++) {
            const int seg = tid + i * 256;
            const int r = seg >> 2, c = seg & 3;
            const uint32_t so = (uint32_t)(r * GST + c * 8) * 2u;
            const size_t go = (size_t)r * K + k0 + c * 8;
            cp16(sb + so,            gAh + go);
            cp16(sb + GBUF + so,     gAl + go);
            cp16(sb + 2*GBUF + so,   gBh + go);
            cp16(sb + 3*GBUF + so,   gBl + go);
        }
        cp_commit();
    };

    float acc[4][4][4] = {};
    const int nch = K >> 5;
    issue(0, 0);

    for (int ch = 0; ch < nch; ch++) {
        cp_wait<0>();
        __syncthreads();
        if (ch + 1 < nch) issue(ch + 1, (ch + 1) & 1);

        const uint32_t sb = su + (uint32_t)(ch & 1) * GSTAGE;
#pragma unroll
        for (int ks = 0; ks < 2; ks++) {
            const int fk = ks * 16 + kc8;
            uint32_t bh[4][2], bl[4][2];
#pragma unroll
            for (int jj = 0; jj < 2; jj++) {
                const uint32_t off = (uint32_t)((wn*32 + jj*16 + lr16) * GST + fk) * 2u;
                ldm_x4(bh[2*jj][0], bh[2*jj+1][0], bh[2*jj][1], bh[2*jj+1][1],
                       sb + 2*GBUF + off);
                ldm_x4(bl[2*jj][0], bl[2*jj+1][0], bl[2*jj][1], bl[2*jj+1][1],
                       sb + 3*GBUF + off);
            }
#pragma unroll
            for (int i = 0; i < 4; i++) {
                const uint32_t off = (uint32_t)((wm*64 + i*16 + lr16) * GST + fk) * 2u;
                uint32_t ah[4], al[4];
                ldm_x4(ah[0], ah[1], ah[2], ah[3], sb + off);
                ldm_x4(al[0], al[1], al[2], al[3], sb + GBUF + off);
#pragma unroll
                for (int j = 0; j < 4; j++) mma16816(acc[i][j], ah, bh[j]);
#pragma unroll
                for (int j = 0; j < 4; j++) mma16816(acc[i][j], ah, bl[j]);
#pragma unroll
                for (int j = 0; j < 4; j++) mma16816(acc[i][j], al, bh[j]);
            }
        }
    }

#pragma unroll
    for (int i = 0; i < 4; i++)
#pragma unroll
        for (int j = 0; j < 4; j++) {
            const int row = by*128 + wm*64 + i*16 + g;
            const int col = bx*128 + wn*32 + j*8 + t4*2;
            float b0 = 0.f, b1 = 0.f;
            if (bias) { b0 = bias[col]; b1 = bias[col + 1]; }
            *(float2*)&C[(size_t)row * ldc + col] =
                make_float2(acc[i][j][0] + b0, acc[i][j][1] + b1);
            *(float2*)&C[(size_t)(row + 8) * ldc + col] =
                make_float2(acc[i][j][2] + b0, acc[i][j][3] + b1);
        }
}

// ---------------------------------------------------------------------------
// RoPE + reshape + bf16 hi/lo split.
// ---------------------------------------------------------------------------
__global__ __launch_bounds__(256) void rope_kernel(
    const float* __restrict__ qkv, const float* __restrict__ pos,
    __nv_bfloat16* __restrict__ qh, __nv_bfloat16* __restrict__ ql,
    __nv_bfloat16* __restrict__ kh, __nv_bfloat16* __restrict__ kl,
    __nv_bfloat16* __restrict__ vTh, __nv_bfloat16* __restrict__ vTl)
{
    const int t0 = blockIdx.x * 128;
    const int bh = blockIdx.y;
    const int b = bh >> 4, h = bh & 15;
    __shared__ float sv[128][65];

    for (int idx = threadIdx.x; idx < 128 * 64; idx += 256) {
        const int t = idx >> 6, d = idx & 63;
        const size_t base = ((size_t)(t0 + t) * 4 + b) * 3072 + h * 64 + d;
        const float qv = qkv[base];
        const float kv = qkv[base + 1024];
        sv[t][d] = qkv[base + 2048];
        float c, s;
        sincosf(pos[(t0 + t) * 64 + d], &s, &c);
        const int po = (d < 32) ? 32 : -32;
        const float rq = (d < 32) ? -qkv[base + po] : qkv[base + po];
        const float rk = (d < 32) ? -qkv[base + 1024 + po] : qkv[base + 1024 + po];
        const float qr = fmaf(qv, c, rq * s) * 0.125f;
        const float kr = fmaf(kv, c, rk * s);
        const size_t o = (size_t)bh * T * D + (size_t)(t0 + t) * 64 + d;
        __nv_bfloat16 hh, ll;
        split_bf(qr, hh, ll); qh[o] = hh; ql[o] = ll;
        split_bf(kr, hh, ll); kh[o] = hh; kl[o] = ll;
    }
    __syncthreads();
    for (int idx = threadIdx.x; idx < 128 * 64; idx += 256) {
        const int d = idx >> 7, t = idx & 127;
        __nv_bfloat16 hh, ll;
        split_bf(sv[t][d], hh, ll);
        const size_t o = ((size_t)bh * 64 + d) * T + t0 + t;
        vTh[o] = hh; vTl[o] = ll;
    }
}

// ---------------------------------------------------------------------------
// Fused attention: S=QK^T -> exp (3/4 MUFU, 1/4 FMA-poly; no max) ->
// attn(unnorm) + rowsums + PV. Double-buffered K/V; one sync per j-tile.
// Q fragments hoisted into registers (loop-invariant; 1 CTA/SM so regs free).
// ---------------------------------------------------------------------------
constexpr int STQ = 72;
constexpr int STV = 136;
constexpr int OQH = 0,  OQL = 18432;
constexpr int OK0 = 36864;                 // + st*36864 (lo at +18432)
constexpr int OV0 = 110592;                // + st*34816 (lo at +17408)
constexpr int FLASH_SMEM = 180224;

__global__ __launch_bounds__(256, 1) void flash_kernel(
    const __nv_bfloat16* __restrict__ qh, const __nv_bfloat16* __restrict__ ql,
    const __nv_bfloat16* __restrict__ kh, const __nv_bfloat16* __restrict__ kl,
    const __nv_bfloat16* __restrict__ vTh, const __nv_bfloat16* __restrict__ vTl,
    float* __restrict__ attn, float* __restrict__ invl_g,
    __nv_bfloat16* __restrict__ cxh, __nv_bfloat16* __restrict__ cxl)
{
    const int by = (gridDim.x - 1) - blockIdx.x;
    const int bh = blockIdx.y;
    const int b = bh >> 4, h = bh & 15;

    extern __shared__ char smc[];
    const uint32_t su = smem_u32(smc);
    __shared__ float sL[2][128];
    __shared__ float sInv[128];

    const int tid = threadIdx.x, lane = tid & 31, wid = tid >> 5;
    const int wm = wid & 3, wn = wid >> 2;
    const int g = lane >> 2, t4 = lane & 3;
    const int lr16 = lane & 15, kc8 = (lane >> 4) << 3;

    const size_t qoff = (size_t)bh * T * D + (size_t)by * 128 * 64;
    const size_t koff = (size_t)bh * T * D;
    const size_t voff = (size_t)bh * D * T;

    auto issueK = [&](int j, int st) {
        const uint32_t sb = su + OK0 + (uint32_t)st * 36864u;
#pragma unroll
        for (int i = 0; i < 4; i++) {
            const int seg = tid + i * 256;
            const int r = seg >> 3, c = seg & 7;
            const uint32_t so = (uint32_t)(r * STQ + c * 8) * 2u;
            cp16(sb + so,         kh + koff + (size_t)(j*128 + r) * 64 + c * 8);
            cp16(sb + 18432 + so, kl + koff + (size_t)(j*128 + r) * 64 + c * 8);
        }
    };
    auto issueV = [&](int j, int st) {
        const uint32_t vb = su + OV0 + (uint32_t)st * 34816u;
#pragma unroll
        for (int i = 0; i < 4; i++) {
            const int seg = tid + i * 256;
            const int d = seg >> 4, c = seg & 15;
            const uint32_t so = (uint32_t)(d * STV + c * 8) * 2u;
            cp16(vb + so,         vTh + voff + (size_t)d * T + j * 128 + c * 8);
            cp16(vb + 17408 + so, vTl + voff + (size_t)d * T + j * 128 + c * 8);
        }
    };

    // prologue: Q + K0 + V0 in one group
#pragma unroll
    for (int i = 0; i < 4; i++) {
        const int seg = tid + i * 256;
        const int r = seg >> 3, c = seg & 7;
        const uint32_t so = (uint32_t)(r * STQ + c * 8) * 2u;
        cp16(su + OQH + so, qh + qoff + (size_t)r * 64 + c * 8);
        cp16(su + OQL + so, ql + qoff + (size_t)r * 64 + c * 8);
    }
    issueK(0, 0);
    issueV(0, 0);
    cp_commit();

    cp_wait<0>();
    __syncthreads();

    // ---- hoist Q fragments (loop-invariant across j) ----
    uint32_t qfh[4][2][4], qfl[4][2][4];
#pragma unroll
    for (int ks = 0; ks < 4; ks++) {
        const int fk = ks * 16 + kc8;
#pragma unroll
        for (int mf = 0; mf < 2; mf++) {
            const uint32_t off = (uint32_t)((wm*32 + mf*16 + lr16) * STQ + fk) * 2u;
            ldm_x4(qfh[ks][mf][0], qfh[ks][mf][1], qfh[ks][mf][2], qfh[ks][mf][3],
                   su + OQH + off);
            ldm_x4(qfl[ks][mf][0], qfl[ks][mf][1], qfl[ks][mf][2], qfl[ks][mf][3],
                   su + OQL + off);
        }
    }

    float l4[4] = {0.f, 0.f, 0.f, 0.f};
    float cacc[2][8][4] = {};

    for (int j = 0; j <= by; j++) {
        const int st = j & 1;
        if (j < by) {
            issueK(j + 1, st ^ 1);
            issueV(j + 1, st ^ 1);
            cp_commit();
        }

        // ---- S = Q Kj^T (bf16x3, Q frags from registers) ----
        float S[2][8][4] = {};
        const uint32_t kbH = su + OK0 + (uint32_t)st * 36864u;
        const uint32_t kbL = kbH + 18432u;
#pragma unroll
        for (int ks = 0; ks < 4; ks++) {
            const int fk = ks * 16 + kc8;
#pragma unroll
            for (int jj = 0; jj < 4; jj++) {
                const uint32_t off = (uint32_t)((wn*64 + jj*16 + lr16) * STQ + fk) * 2u;
                uint32_t bhf[2][2], blf[2][2];
                ldm_x4(bhf[0][0], bhf[1][0], bhf[0][1], bhf[1][1], kbH + off);
                ldm_x4(blf[0][0], blf[1][0], blf[0][1], blf[1][1], kbL + off);
#pragma unroll
                for (int mf = 0; mf < 2; mf++)
#pragma unroll
                    for (int n2 = 0; n2 < 2; n2++)
                        mma16816(S[mf][2*jj + n2], qfh[ks][mf], bhf[n2]);
#pragma unroll
                for (int mf = 0; mf < 2; mf++)
#pragma unroll
                    for (int n2 = 0; n2 < 2; n2++)
                        mma16816(S[mf][2*jj + n2], qfh[ks][mf], blf[n2]);
#pragma unroll
                for (int mf = 0; mf < 2; mf++)
#pragma unroll
                    for (int n2 = 0; n2 < 2; n2++)
                        mma16816(S[mf][2*jj + n2], qfl[ks][mf], bhf[n2]);
            }
        }

        // ---- exp (3/4 MUFU, 1/4 FMA poly), mask, l accum, attn store ----
        const int rowbase = by * 128 + wm * 32;
        const int colbase = j * 128 + wn * 64;
        float* ap = attn + (size_t)bh * T * T;
#pragma unroll
        for (int mf = 0; mf < 2; mf++)
#pragma unroll
            for (int nf = 0; nf < 8; nf++) {
                const int row0 = rowbase + mf * 16 + g;
                const int col = colbase + nf * 8 + t4 * 2;
#pragma unroll
                for (int c = 0; c < 4; c++) {
                    const int rr = row0 + ((c >= 2) ? 8 : 0);
                    const int cc = col + (c & 1);
                    float e = (c == 3) ? exp_poly(S[mf][nf][c])
                                       : __expf(S[mf][nf][c]);
                    if (j == by && cc > rr) e = 0.f;
                    S[mf][nf][c] = e;
                    l4[mf * 2 + (c >= 2)] += e;
                }
                *(float2*)&ap[(size_t)row0 * T + col] =
                    make_float2(S[mf][nf][0], S[mf][nf][1]);
                *(float2*)&ap[(size_t)(row0 + 8) * T + col] =
                    make_float2(S[mf][nf][2], S[mf][nf][3]);
            }

        // ---- PV ----
        const uint32_t vbH = su + OV0 + (uint32_t)st * 34816u;
        const uint32_t vbL = vbH + 17408u;
#pragma unroll
        for (int kf = 0; kf < 4; kf++) {
            uint32_t aPh[2][4], aPl[2][4];
#pragma unroll
            for (int mf = 0; mf < 2; mf++) {
                const float* p0 = S[mf][2*kf];
                const float* p1 = S[mf][2*kf + 1];
                __nv_bfloat16 hh[8], ll[8];
                split_bf(p0[0], hh[0], ll[0]); split_bf(p0[1], hh[1], ll[1]);
                split_bf(p0[2], hh[2], ll[2]); split_bf(p0[3], hh[3], ll[3]);
                split_bf(p1[0], hh[4], ll[4]); split_bf(p1[1], hh[5], ll[5]);
                split_bf(p1[2], hh[6], ll[6]); split_bf(p1[3], hh[7], ll[7]);
                aPh[mf][0] = packbf2(hh[0], hh[1]); aPh[mf][1] = packbf2(hh[2], hh[3]);
                aPh[mf][2] = packbf2(hh[4], hh[5]); aPh[mf][3] = packbf2(hh[6], hh[7]);
                aPl[mf][0] = packbf2(ll[0], ll[1]); aPl[mf][1] = packbf2(ll[2], ll[3]);
                aPl[mf][2] = packbf2(ll[4], ll[5]); aPl[mf][3] = packbf2(ll[6], ll[7]);
            }
#pragma unroll
            for (int jj = 0; jj < 4; jj++) {
                const uint32_t off =
                    (uint32_t)((jj*16 + lr16) * STV + wn*64 + kf*16 + kc8) * 2u;
                uint32_t vh[2][2], vl[2][2];
                ldm_x4(vh[0][0], vh[1][0], vh[0][1], vh[1][1], vbH + off);
                ldm_x4(vl[0][0], vl[1][0], vl[0][1], vl[1][1], vbL + off);
#pragma unroll
                for (int mf = 0; mf < 2; mf++)
#pragma unroll
                    for (int n2 = 0; n2 < 2; n2++)
                        mma16816(cacc[mf][2*jj + n2], aPh[mf], vh[n2]);
#pragma unroll
                for (int mf = 0; mf < 2; mf++)
#pragma unroll
                    for (int n2 = 0; n2 < 2; n2++)
                        mma16816(cacc[mf][2*jj + n2], aPh[mf], vl[n2]);
#pragma unroll
                for (int mf = 0; mf < 2; mf++)
#pragma unroll
                    for (int n2 = 0; n2 < 2; n2++)
                        mma16816(cacc[mf][2*jj + n2], aPl[mf], vh[n2]);
            }
        }

        // wait for next tile's K/V; all warps done with stage st
        if (j < by) {
            cp_wait<0>();
            __syncthreads();
        }
    }

    // ---- row sums ----
#pragma unroll
    for (int r4 = 0; r4 < 4; r4++) {
        l4[r4] += __shfl_xor_sync(0xffffffffu, l4[r4], 1);
        l4[r4] += __shfl_xor_sync(0xffffffffu, l4[r4], 2);
    }
    if (t4 == 0) {
#pragma unroll
        for (int mf = 0; mf < 2; mf++)
#pragma unroll
            for (int hf = 0; hf < 2; hf++)
                sL[wn][wm*32 + mf*16 + g + hf*8] = l4[mf*2 + hf];
    }
    __syncthreads();
    if (tid < 128) {
        const float iv = 1.f / (sL[0][tid] + sL[1][tid]);
        sInv[tid] = iv;
        invl_g[(size_t)bh * T + by * 128 + tid] = iv;
    }

    // ---- zero-fill causal upper region ----
    {
        const int cstart = (by + 1) * 128;
        const int w4 = (T - cstart) >> 2;
        float* ap = attn + (size_t)bh * T * T;
        for (int idx = tid; idx < 128 * w4; idx += 256) {
            const int r = idx / w4, c4 = idx - r * w4;
            *(float4*)&ap[(size_t)(by*128 + r) * T + cstart + c4*4] =
                make_float4(0.f, 0.f, 0.f, 0.f);
        }
    }
    __syncthreads();

    // ---- cross-wn ctx reduce + normalize + split-store ----
    float* sRed = (float*)(smc + OK0);
    if (wn == 1) {
#pragma unroll
        for (int mf = 0; mf < 2; mf++)
#pragma unroll
            for (int nf = 0; nf < 8; nf++) {
                const int lr = wm*32 + mf*16 + g;
                const int col = nf*8 + t4*2;
                sRed[lr*64 + col]       = cacc[mf][nf][0];
                sRed[lr*64 + col + 1]   = cacc[mf][nf][1];
                sRed[(lr+8)*64 + col]   = cacc[mf][nf][2];
                sRed[(lr+8)*64 + col+1] = cacc[mf][nf][3];
            }
    }
    __syncthreads();
    if (wn == 0) {
#pragma unroll
        for (int mf = 0; mf < 2; mf++)
#pragma unroll
            for (int nf = 0; nf < 8; nf++) {
                const int lr = wm*32 + mf*16 + g;
                const int col = nf*8 + t4*2;
                const float iv0 = sInv[lr], iv1 = sInv[lr + 8];
                const float v0 = (cacc[mf][nf][0] + sRed[lr*64 + col])     * iv0;
                const float v1 = (cacc[mf][nf][1] + sRed[lr*64 + col + 1]) * iv0;
                const float v2 = (cacc[mf][nf][2] + sRed[(lr+8)*64 + col])     * iv1;
                const float v3 = (cacc[mf][nf][3] + sRed[(lr+8)*64 + col + 1]) * iv1;
                __nv_bfloat16 h0,h1,h2,h3,l0,l1,l2,l3;
                split_bf(v0,h0,l0); split_bf(v1,h1,l1);
                split_bf(v2,h2,l2); split_bf(v3,h3,l3);
                const size_t o0 = ((size_t)(by*128 + lr)   * 4 + b) * 1024 + h*64 + col;
                const size_t o1 = ((size_t)(by*128 + lr+8) * 4 + b) * 1024 + h*64 + col;
                *(uint32_t*)&cxh[o0] = packbf2(h0, h1);
                *(uint32_t*)&cxl[o0] = packbf2(l0, l1);
                *(uint32_t*)&cxh[o1] = packbf2(h2, h3);
                *(uint32_t*)&cxl[o1] = packbf2(l2, l3);
            }
    }
}

// ---------------------------------------------------------------------------
// Rescale: attn[bh][t][0..t] *= invl[bh][t].  8 rows per block (R12 form).
// ---------------------------------------------------------------------------
__global__ __launch_bounds__(256) void rescale_kernel(
    float* __restrict__ attn, const float* __restrict__ invl)
{
    const int bh = blockIdx.y;
    const int t0 = blockIdx.x * 8;
#pragma unroll
    for (int r = 0; r < 8; r++) {
        const int t = t0 + r;
        const float iv = invl[(size_t)bh * T + t];
        float* rowp = attn + (size_t)bh * T * T + (size_t)t * T;
        const int L = t + 1;
        const int n4 = L >> 2;
        float4* r4 = (float4*)rowp;
        for (int i = threadIdx.x; i < n4; i += 256) {
            float4 v = r4[i];
            v.x *= iv; v.y *= iv; v.z *= iv; v.w *= iv;
            r4[i] = v;
        }
        const int tail = n4 * 4 + threadIdx.x;
        if (tail < L) rowp[tail] *= iv;
    }
}

// ---------------------------------------------------------------------------
extern "C" void kernel_launch(void* const* d_in, const int* in_sizes, int n_in,
                              void* d_out, int out_size)
{
    const float* input = (const float*)d_in[0];
    const float* pos   = (const float*)d_in[1];
    const float* in_w  = (const float*)d_in[2];
    const float* in_b  = (const float*)d_in[3];
    const float* out_w = (const float*)d_in[4];
    const float* out_b = (const float*)d_in[5];
    float* out = (float*)d_out;

    float *qkv, *attn_s, *invl;
    __nv_bfloat16 *inh, *inl, *wih, *wil, *woh, *wol;
    __nv_bfloat16 *qh, *ql, *kh, *kl, *vTh, *vTl, *cxh, *cxl;
    cudaGetSymbolAddress((void**)&qkv,    g_qkv);
    cudaGetSymbolAddress((void**)&attn_s, g_attn);
    cudaGetSymbolAddress((void**)&invl,   g_invl);
    cudaGetSymbolAddress((void**)&inh, g_inh); cudaGetSymbolAddress((void**)&inl, g_inl);
    cudaGetSymbolAddress((void**)&wih, g_wih); cudaGetSymbolAddress((void**)&wil, g_wil);
    cudaGetSymbolAddress((void**)&woh, g_woh); cudaGetSymbolAddress((void**)&wol, g_wol);
    cudaGetSymbolAddress((void**)&qh,  g_qh);  cudaGetSymbolAddress((void**)&ql,  g_ql);
    cudaGetSymbolAddress((void**)&kh,  g_kh);  cudaGetSymbolAddress((void**)&kl,  g_kl);
    cudaGetSymbolAddress((void**)&vTh, g_vTh); cudaGetSymbolAddress((void**)&vTl, g_vTl);
    cudaGetSymbolAddress((void**)&cxh, g_cxh); cudaGetSymbolAddress((void**)&cxl, g_cxl);

    float* attn = ((size_t)out_size >= OUT_ELEMS + ATTN_ELEMS)
                      ? (out + OUT_ELEMS) : attn_s;

    cudaFuncSetAttribute(flash_kernel,
                         cudaFuncAttributeMaxDynamicSharedMemorySize, FLASH_SMEM);
    cudaFuncSetAttribute(gemm_bf,
                         cudaFuncAttributeMaxDynamicSharedMemorySize, GEMM_SMEM);

    // 0) pre-split GEMM operands
    split_kernel<<<(int)(OUT_ELEMS / 2048), 256>>>(input, inh, inl, (int)OUT_ELEMS);
    split_kernel<<<3 * E * E / 2048, 256>>>(in_w, wih, wil, 3 * E * E);
    split_kernel<<<E * E / 2048, 256>>>(out_w, woh, wol, E * E);

    // 1) fused QKV projection (128x128 tiles, 2 CTAs/SM)
    gemm_bf<<<dim3(3 * E / 128, T * B / 128), 256, GEMM_SMEM>>>(
        inh, inl, wih, wil, in_b, qkv, E, 3 * E);

    // 2) RoPE + reshape + bf16 split
    rope_kernel<<<dim3(T / 128, BH), 256>>>(qkv, pos, qh, ql, kh, kl, vTh, vTl);

    // 3) fused attention (Q frags hoisted, 1/4 poly exp)
    flash_kernel<<<dim3(T / 128, BH), 256, FLASH_SMEM>>>(
        qh, ql, kh, kl, vTh, vTl, attn, invl, cxh, cxl);

    // 4) normalize attn rows
    rescale_kernel<<<dim3(T / 8, BH), 256>>>(attn, invl);

    // 5) output projection
    gemm_bf<<<dim3(E / 128, T * B / 128), 256, GEMM_SMEM>>>(
        cxh, cxl, woh, wol, out_b, out, E, E);
}